// round 3
// baseline (speedup 1.0000x reference)
#include <cuda_runtime.h>

namespace {

constexpr int H  = 64;
constexpr int Fd = 8;
constexpr int Tn = 512;
constexpr int Pn = 64;
constexpr int NB = 4;       // batch rows per CTA
constexpr int NT = 256;     // threads per CTA

using u64 = unsigned long long;

__device__ __forceinline__ u64 ffma2(u64 a, u64 b, u64 c) {
    u64 d;
    asm("fma.rn.f32x2 %0, %1, %2, %3;" : "=l"(d) : "l"(a), "l"(b), "l"(c));
    return d;
}
__device__ __forceinline__ u64 pack2(float lo, float hi) {
    u64 d;
    asm("mov.b64 %0, {%1, %2};" : "=l"(d) : "f"(lo), "f"(hi));
    return d;
}
__device__ __forceinline__ float hsum2(u64 v) {
    float lo, hi;
    asm("mov.b64 {%0, %1}, %2;" : "=f"(lo), "=f"(hi) : "l"(v));
    return lo + hi;
}
__device__ __forceinline__ float sigf(float x) {
    return 1.0f / (1.0f + __expf(-x));
}
__device__ __forceinline__ float tanh_fast(float x) {
    return 2.0f / (1.0f + __expf(-2.0f * x)) - 1.0f;
}

// Load per-thread weights: 4 gate rows (g*64+u), k-quarter q, chunk-rotated
// so compute can index weights statically while h loads rotate banks.
__device__ __forceinline__ void load_weights(
    const float* __restrict__ Whh, const float* __restrict__ Wih,
    const float* __restrict__ bih, const float* __restrict__ bhh,
    int u, int q, u64 wh[4][8], u64 wx[4], float bq[4])
{
#pragma unroll
    for (int g = 0; g < 4; g++) {
        int row = g * 64 + u;
        const float* wr = Whh + row * H + 16 * q;
#pragma unroll
        for (int d = 0; d < 4; d++) {
            int dd = (d + q) & 3;
            ulonglong2 v = __ldg((const ulonglong2*)(wr + 4 * dd));
            wh[g][2 * d]     = v.x;
            wh[g][2 * d + 1] = v.y;
        }
        wx[g] = __ldg((const u64*)(Wih + row * Fd) + q);
        bq[g] = 0.25f * (bih[row] + bhh[row]);   // each of 4 lanes adds a quarter
    }
}

// One LSTM step: gates via split-k FFMA2, shfl-reduce over the 4-lane group,
// activation + c update + h store by the owning lane. Single barrier lives
// in the caller (ping-pong buffers make this safe).
__device__ __forceinline__ void lstm_step(
    const float (*__restrict__ shc)[H], const float (*__restrict__ sxc)[Fd],
    float (*__restrict__ shn)[H],
    const u64 wh[4][8], const u64 wx[4], const float bq[4],
    const int koff[4], int q, int u, float& c)
{
#pragma unroll
    for (int chunk = 0; chunk < 2; chunk++) {
        u64 acc[4][2];
#pragma unroll
        for (int g = 0; g < 4; g++) {
            u64 b0 = pack2(bq[g], 0.0f);
            acc[g][0] = b0; acc[g][1] = b0;
        }
#pragma unroll
        for (int i = 0; i < 2; i++) {
            int b = 2 * chunk + i;
            // x contribution: this lane's 2 features (split over 4 lanes)
            u64 xv = *(const u64*)(&sxc[b][0] + 2 * q);
#pragma unroll
            for (int g = 0; g < 4; g++) acc[g][i] = ffma2(wx[g], xv, acc[g][i]);
            // h contribution: this lane's 16-value k-quarter, rotated chunks
            const float* hrow = &shc[b][0];
#pragma unroll
            for (int d = 0; d < 4; d++) {
                ulonglong2 hv = *(const ulonglong2*)(hrow + koff[d]);
#pragma unroll
                for (int g = 0; g < 4; g++) {
                    acc[g][i] = ffma2(wh[g][2 * d],     hv.x, acc[g][i]);
                    acc[g][i] = ffma2(wh[g][2 * d + 1], hv.y, acc[g][i]);
                }
            }
        }
        // reduce across the 4-lane group; lane q ends with all 4 gates for
        // batch row b = 2*chunk + (q&1)
        float p0[4], p1[4], t[4];
#pragma unroll
        for (int g = 0; g < 4; g++) { p0[g] = hsum2(acc[g][0]); p1[g] = hsum2(acc[g][1]); }
        int keep = q & 1;
#pragma unroll
        for (int g = 0; g < 4; g++) {
            float send = keep ? p0[g] : p1[g];
            float mine = keep ? p1[g] : p0[g];
            float r = __shfl_xor_sync(0xffffffffu, send, 1);
            t[g] = mine + r;
        }
#pragma unroll
        for (int g = 0; g < 4; g++) t[g] += __shfl_xor_sync(0xffffffffu, t[g], 2);

        if ((q >> 1) == chunk) {   // lane q owns (u, b=q)
            float ig = sigf(t[0]);
            float fg = sigf(t[1]);
            float gg = tanh_fast(t[2]);
            float og = sigf(t[3]);
            c = fg * c + ig * gg;
            shn[q][u] = og * tanh_fast(c);
        }
    }
}

__global__ void __launch_bounds__(NT, 2)
seq2seq_lstm_kernel(
    const float* __restrict__ input,   // [B, T, F]
    const float* __restrict__ eWih, const float* __restrict__ eWhh,
    const float* __restrict__ ebih, const float* __restrict__ ebhh,
    const float* __restrict__ dWih, const float* __restrict__ dWhh,
    const float* __restrict__ dbih, const float* __restrict__ dbhh,
    const float* __restrict__ fcW,  const float* __restrict__ fcb,
    float* __restrict__ out)           // [B, P, F]
{
    __shared__ float sh[2][NB][H];     // ping-pong hidden state
    __shared__ float sx[2][NB][Fd];    // ping-pong input
    __shared__ float sfcW[Fd][H];
    __shared__ float sfcb[Fd];

    const int tid = threadIdx.x;
    const int b0  = blockIdx.x * NB;
    const int u   = tid >> 2;          // hidden unit (0..63)
    const int q   = tid & 3;           // lane role: k-quarter / owned batch row

    // fc weights into shared
    ((float*)sfcW)[tid]      = fcW[tid];
    ((float*)sfcW)[tid + NT] = fcW[tid + NT];
    if (tid < Fd) sfcb[tid] = fcb[tid];

    // init state
    sh[0][q][u] = 0.0f;
    float c = 0.0f;

    int koff[4];
#pragma unroll
    for (int d = 0; d < 4; d++) koff[d] = 16 * q + 4 * ((d + q) & 3);

    u64 wh[4][8], wx[4];
    float bq[4];
    load_weights(eWhh, eWih, ebih, ebhh, u, q, wh, wx, bq);

    const bool xth = tid < NB * Fd;
    const int  xb  = tid >> 3;
    const int  xf  = tid & 7;
    const float* xptr = input + (size_t)(b0 + xb) * Tn * Fd + xf;
    float xreg = xth ? __ldg(xptr) : 0.0f;

    int cur = 0;

    // =================== encoder ===================
    for (int t = 0; t < Tn; t++) {
        if (xth) sx[cur][xb][xf] = xreg;
        __syncthreads();   // h(prev) in sh[cur], x(t) in sx[cur]
        if (xth && t + 1 < Tn) xreg = __ldg(xptr + (size_t)(t + 1) * Fd);

        lstm_step(sh[cur], sx[cur], sh[cur ^ 1], wh, wx, bq, koff, q, u, c);
        cur ^= 1;
    }
    // after 512 steps: cur == 0, final h in sh[0], x_last in sx[1] == sx[cur^1]

    load_weights(dWhh, dWih, dbih, dbhh, u, q, wh, wx, bq);

    // =================== decoder ===================
    for (int p = 0; p < Pn; p++) {
        __syncthreads();   // h in sh[cur], x in sx[cur^1]

        lstm_step(sh[cur], sx[cur ^ 1], sh[cur ^ 1], wh, wx, bq, koff, q, u, c);

        __syncthreads();   // h_new complete in sh[cur^1]

        if (xth) {         // pred = h_new @ fcW^T + fcb
            float a = sfcb[xf];
            const float4* hr = (const float4*)&sh[cur ^ 1][xb][0];
            const float4* wr = (const float4*)&sfcW[xf][0];
#pragma unroll
            for (int k = 0; k < 16; k++) {
                float4 hv = hr[k], wv = wr[k];
                a = fmaf(hv.x, wv.x, a);
                a = fmaf(hv.y, wv.y, a);
                a = fmaf(hv.z, wv.z, a);
                a = fmaf(hv.w, wv.w, a);
            }
            out[((size_t)(b0 + xb) * Pn + p) * Fd + xf] = a;
            sx[cur][xb][xf] = a;   // x for next decoder step
        }
        cur ^= 1;
        // next iteration's first barrier orders the sx write
    }
}

} // anonymous namespace

extern "C" void kernel_launch(void* const* d_in, const int* in_sizes, int n_in,
                              void* d_out, int out_size)
{
    const float* input = (const float*)d_in[0];
    const float* eWih  = (const float*)d_in[1];
    const float* eWhh  = (const float*)d_in[2];
    const float* ebih  = (const float*)d_in[3];
    const float* ebhh  = (const float*)d_in[4];
    const float* dWih  = (const float*)d_in[5];
    const float* dWhh  = (const float*)d_in[6];
    const float* dbih  = (const float*)d_in[7];
    const float* dbhh  = (const float*)d_in[8];
    const float* fcW   = (const float*)d_in[9];
    const float* fcb   = (const float*)d_in[10];
    float* out = (float*)d_out;

    const int B = 1024;
    seq2seq_lstm_kernel<<<B / NB, NT>>>(input, eWih, eWhh, ebih, ebhh,
                                        dWih, dWhh, dbih, dbhh, fcW, fcb, out);
}

// round 4
// speedup vs baseline: 1.3762x; 1.3762x over previous
#include <cuda_runtime.h>

namespace {

constexpr int H  = 64;
constexpr int Fd = 8;
constexpr int Tn = 512;
constexpr int Pn = 64;
constexpr int NT = 256;     // threads per CTA (one per gate row)
constexpr int NBMAX = 4;

using u64 = unsigned long long;

__device__ __forceinline__ u64 ffma2(u64 a, u64 b, u64 c) {
    u64 d;
    asm("fma.rn.f32x2 %0, %1, %2, %3;" : "=l"(d) : "l"(a), "l"(b), "l"(c));
    return d;
}
__device__ __forceinline__ u64 pack2(float lo, float hi) {
    u64 d;
    asm("mov.b64 %0, {%1, %2};" : "=l"(d) : "f"(lo), "f"(hi));
    return d;
}
__device__ __forceinline__ float hsum2(u64 v) {
    float lo, hi;
    asm("mov.b64 {%0, %1}, %2;" : "=f"(lo), "=f"(hi) : "l"(v));
    return lo + hi;
}
__device__ __forceinline__ float tanh_approx(float x) {
    float y;
    asm("tanh.approx.f32 %0, %1;" : "=f"(y) : "f"(x));
    return y;
}
// sigmoid via hw tanh: 1 MUFU instead of 2
__device__ __forceinline__ float sig_a(float x) {
    return fmaf(tanh_approx(0.5f * x), 0.5f, 0.5f);
}
// precise-ish tanh for the cell path
__device__ __forceinline__ float tanh_e(float x) {
    return 2.0f / (1.0f + __expf(-2.0f * x)) - 1.0f;
}

__device__ __forceinline__ void load_w(
    const float* __restrict__ Whh, const float* __restrict__ Wih,
    const float* __restrict__ bih, const float* __restrict__ bhh,
    int j, u64 w2[32], u64 wx[4], u64& bias2)
{
    const ulonglong2* wp = (const ulonglong2*)(Whh + j * H);
#pragma unroll
    for (int k = 0; k < 16; k++) {
        ulonglong2 v = __ldg(wp + k);
        w2[2 * k] = v.x; w2[2 * k + 1] = v.y;
    }
    const ulonglong2* wi = (const ulonglong2*)(Wih + j * Fd);
    ulonglong2 v0 = __ldg(wi), v1 = __ldg(wi + 1);
    wx[0] = v0.x; wx[1] = v0.y; wx[2] = v1.x; wx[3] = v1.y;
    bias2 = pack2(bih[j] + bhh[j], 0.0f);
}

template<int NB_>
__device__ __forceinline__ void gate_mm(
    const u64 w2[32], const u64 wx[4], u64 bias2,
    const float (*__restrict__ sh)[H], const float (*__restrict__ sx)[Fd],
    u64 acc[NB_])
{
    // x contribution first (loads issue while h pipeline starts)
#pragma unroll
    for (int b = 0; b < NB_; b++) {
        ulonglong2 xa = *(const ulonglong2*)&sx[b][0];
        ulonglong2 xb = *(const ulonglong2*)&sx[b][4];
        u64 a = ffma2(wx[0], xa.x, bias2);
        a = ffma2(wx[1], xa.y, a);
        a = ffma2(wx[2], xb.x, a);
        a = ffma2(wx[3], xb.y, a);
        acc[b] = a;
    }
    // h contribution: 2-stage pipelined over kc chunks of 4 floats
    ulonglong2 hv[2][NB_];
#pragma unroll
    for (int b = 0; b < NB_; b++) hv[0][b] = *(const ulonglong2*)&sh[b][0];
#pragma unroll
    for (int kc = 0; kc < 16; kc++) {
        const int cur = kc & 1, nxt = cur ^ 1;
        if (kc < 15) {
#pragma unroll
            for (int b = 0; b < NB_; b++)
                hv[nxt][b] = *(const ulonglong2*)&sh[b][(kc + 1) * 4];
        }
        u64 wlo = w2[2 * kc], whi = w2[2 * kc + 1];
#pragma unroll
        for (int b = 0; b < NB_; b++) {
            acc[b] = ffma2(wlo, hv[cur][b].x, acc[b]);
            acc[b] = ffma2(whi, hv[cur][b].y, acc[b]);
        }
    }
}

template<int NB_>
__device__ __forceinline__ void run_lstm(
    int b0,
    const float* __restrict__ input,
    const float* __restrict__ eWih, const float* __restrict__ eWhh,
    const float* __restrict__ ebih, const float* __restrict__ ebhh,
    const float* __restrict__ dWih, const float* __restrict__ dWhh,
    const float* __restrict__ dbih, const float* __restrict__ dbhh,
    const float* __restrict__ fcW,  const float* __restrict__ fcb,
    float* __restrict__ out,
    float (*__restrict__ sh)[H], float (*__restrict__ sg)[4 * H],
    float (*__restrict__ sx)[Fd], float (*__restrict__ sfcW)[H],
    float* __restrict__ sfcb)
{
    const int tid = threadIdx.x;
    const int j   = tid;             // gate row
    const int ub  = tid >> 6;        // update-phase batch row
    const int uu  = tid & (H - 1);   // update-phase hidden unit

    // fc weights into shared
    ((float*)sfcW)[tid]      = fcW[tid];
    ((float*)sfcW)[tid + NT] = fcW[tid + NT];
    if (tid < Fd) sfcb[tid] = fcb[tid];

    sh[ub][uu] = 0.0f;
    float c = 0.0f;

    u64 w2[32], wx[4], bias2;
    load_w(eWhh, eWih, ebih, ebhh, j, w2, wx, bias2);

    const bool xth = tid < NB_ * Fd;
    const int  xb  = tid >> 3;
    const int  xf  = tid & 7;
    const float* xptr = input + (size_t)(b0 + (xth ? xb : 0)) * Tn * Fd + xf;
    float xreg = xth ? __ldg(xptr) : 0.0f;

    // =================== encoder ===================
    for (int t = 0; t < Tn; t++) {
        if (xth) sx[xb][xf] = xreg;
        __syncthreads();   // x(t) stored; h(t-1) visible
        if (xth && t + 1 < Tn) xreg = __ldg(xptr + (size_t)(t + 1) * Fd);

        u64 acc[NB_];
        gate_mm<NB_>(w2, wx, bias2, sh, sx, acc);
#pragma unroll
        for (int b = 0; b < NB_; b++) sg[b][j] = hsum2(acc[b]);
        __syncthreads();   // gates complete

        if (ub < NB_) {
            float gi = sg[ub][uu];
            float gf = sg[ub][H + uu];
            float gg = sg[ub][2 * H + uu];
            float go = sg[ub][3 * H + uu];
            float i_ = sig_a(gi), f_ = sig_a(gf), o_ = sig_a(go);
            c = f_ * c + i_ * tanh_e(gg);
            sh[ub][uu] = o_ * tanh_e(c);
        }
        // next iteration's first barrier orders this write
    }

    load_w(dWhh, dWih, dbih, dbhh, j, w2, wx, bias2);
    __syncthreads();  // final h visible; sx holds x[:, T-1, :]

    // =================== decoder ===================
    for (int p = 0; p < Pn; p++) {
        u64 acc[NB_];
        gate_mm<NB_>(w2, wx, bias2, sh, sx, acc);
#pragma unroll
        for (int b = 0; b < NB_; b++) sg[b][j] = hsum2(acc[b]);
        __syncthreads();   // gates complete

        if (ub < NB_) {
            float gi = sg[ub][uu];
            float gf = sg[ub][H + uu];
            float gg = sg[ub][2 * H + uu];
            float go = sg[ub][3 * H + uu];
            float i_ = sig_a(gi), f_ = sig_a(gf), o_ = sig_a(go);
            c = f_ * c + i_ * tanh_e(gg);
            sh[ub][uu] = o_ * tanh_e(c);
        }
        __syncthreads();   // h update complete

        if (xth) {         // pred = h @ fcW^T + fcb
            float a = sfcb[xf];
            const float4* hr = (const float4*)&sh[xb][0];
            const float4* wr = (const float4*)&sfcW[xf][0];
#pragma unroll
            for (int k = 0; k < 16; k++) {
                float4 hv = hr[k], wv = wr[k];
                a = fmaf(hv.x, wv.x, a);
                a = fmaf(hv.y, wv.y, a);
                a = fmaf(hv.z, wv.z, a);
                a = fmaf(hv.w, wv.w, a);
            }
            out[((size_t)(b0 + xb) * Pn + p) * Fd + xf] = a;
            sx[xb][xf] = a;
        }
        __syncthreads();   // pred visible
    }
}

// grid = 296 (2 CTAs on every SM). 136 CTAs carry 4 rows, 160 carry 3:
// 136*4 + 160*3 = 1024. With (bid, bid+148) SM-pairing, each SM hosts
// (4,3) or (3,3) -> max 7 rows/SM vs 8 before.
__global__ void __launch_bounds__(NT, 2)
seq2seq_lstm_kernel(
    const float* __restrict__ input,
    const float* __restrict__ eWih, const float* __restrict__ eWhh,
    const float* __restrict__ ebih, const float* __restrict__ ebhh,
    const float* __restrict__ dWih, const float* __restrict__ dWhh,
    const float* __restrict__ dbih, const float* __restrict__ dbhh,
    const float* __restrict__ fcW,  const float* __restrict__ fcb,
    float* __restrict__ out)
{
    __shared__ float sh[NBMAX][H];
    __shared__ float sg[NBMAX][4 * H];
    __shared__ float sx[NBMAX][Fd];
    __shared__ float sfcW[Fd][H];
    __shared__ float sfcb[Fd];

    const int bid = blockIdx.x;
    if (bid < 136) {
        run_lstm<4>(4 * bid, input, eWih, eWhh, ebih, ebhh,
                    dWih, dWhh, dbih, dbhh, fcW, fcb, out,
                    sh, sg, sx, sfcW, sfcb);
    } else {
        int b0 = (bid < 148) ? (544 + 3 * (bid - 136))
                             : (580 + 3 * (bid - 148));
        run_lstm<3>(b0, input, eWih, eWhh, ebih, ebhh,
                    dWih, dWhh, dbih, dbhh, fcW, fcb, out,
                    sh, sg, sx, sfcW, sfcb);
    }
}

} // anonymous namespace

extern "C" void kernel_launch(void* const* d_in, const int* in_sizes, int n_in,
                              void* d_out, int out_size)
{
    const float* input = (const float*)d_in[0];
    const float* eWih  = (const float*)d_in[1];
    const float* eWhh  = (const float*)d_in[2];
    const float* ebih  = (const float*)d_in[3];
    const float* ebhh  = (const float*)d_in[4];
    const float* dWih  = (const float*)d_in[5];
    const float* dWhh  = (const float*)d_in[6];
    const float* dbih  = (const float*)d_in[7];
    const float* dbhh  = (const float*)d_in[8];
    const float* fcW   = (const float*)d_in[9];
    const float* fcb   = (const float*)d_in[10];
    float* out = (float*)d_out;

    seq2seq_lstm_kernel<<<296, NT>>>(input, eWih, eWhh, ebih, ebhh,
                                     dWih, dWhh, dbih, dbhh, fcW, fcb, out);
}